// round 4
// baseline (speedup 1.0000x reference)
#include <cuda_runtime.h>
#include <math.h>

#define Bz   128
#define Sz   30
#define Hs   768
#define Is   3072
#define NHh  12
#define HDd  64
#define TOK  (Bz*Sz)     // 3840
#define Ee   15
#define Dd   14
#define Rr   29
#define LRr  8
#define LORA_SCAL 2.0f

// ---------------- scratch (static __device__, no allocations) ----------------
__device__ float d_h    [TOK*Hs];
__device__ float d_nx   [TOK*Hs];
__device__ float d_qb   [TOK*Hs];
__device__ float d_kb   [TOK*Hs];
__device__ float d_vb   [TOK*Hs];
__device__ float d_attc [TOK*Hs];   // attention context (pre O-proj)
__device__ float d_att  [TOK*Hs];   // post O-proj (needed by classifier)
__device__ float d_res1 [TOK*Hs];
__device__ float d_nres [TOK*Hs];
__device__ float d_hid  [TOK*Is];   // base_hidden (post-gelu FFN up)
__device__ float d_bout [TOK*Hs];   // base_out
__device__ float d_t1   [TOK*(Ee*LRr)];   // nres @ Au_all^T
__device__ float d_g    [TOK*(Ee*LRr)];   // base_hidden @ Ad_all^T
__device__ float d_pooled[Dd*Bz*Hs];
__device__ float d_coef [TOK*Ee];
__device__ float d_M    [Ee*LRr*LRr];     // per even layer: Ad_e @ Bu_e (8x8)
__device__ float d_maskf[Rr*Dd];
__device__ float d_cnt  [Dd];
__device__ float d_actd [Bz*Dd];

// ---------------- helpers ----------------
__device__ __forceinline__ float gelu_exact(float x){
    return 0.5f * x * (1.f + erff(x * 0.70710678118654752f));
}

// ---------------- build initial h = [cls ; region_features] ----------------
__global__ void k_build(const float* __restrict__ region, const float* __restrict__ cls,
                        float* __restrict__ h){
    int i = blockIdx.x*256 + threadIdx.x;
    if (i >= TOK*Hs) return;
    int t = i / Hs, hh = i % Hs;
    int b = t / Sz, s = t % Sz;
    h[i] = (s == 0) ? cls[hh] : region[((size_t)b*Rr + (s-1))*Hs + hh];
}

// ---------------- elementwise add ----------------
__global__ void k_add(const float* __restrict__ a, const float* __restrict__ b,
                      float* __restrict__ c, int n){
    int i = blockIdx.x*256 + threadIdx.x;
    if (i < n) c[i] = a[i] + b[i];
}

// ---------------- layernorm over H=768 (256 thr, 3 elems/thread) ----------------
__global__ void k_ln(const float* __restrict__ x, float* __restrict__ y,
                     const float* __restrict__ g, const float* __restrict__ b, float eps){
    int t = blockIdx.x, tid = threadIdx.x;
    const float* xr = x + (size_t)t*Hs;
    float v0 = xr[tid], v1 = xr[tid+256], v2 = xr[tid+512];
    __shared__ float red[256], red2[256], mi[2];
    red[tid]  = v0+v1+v2;
    red2[tid] = v0*v0+v1*v1+v2*v2;
    __syncthreads();
    for (int st = 128; st > 0; st >>= 1){
        if (tid < st){ red[tid]+=red[tid+st]; red2[tid]+=red2[tid+st]; }
        __syncthreads();
    }
    if (tid == 0){
        float m = red[0]/768.f;
        float var = red2[0]/768.f - m*m;
        mi[0] = m; mi[1] = rsqrtf(var + eps);
    }
    __syncthreads();
    float m = mi[0], inv = mi[1];
    float* yr = y + (size_t)t*Hs;
    yr[tid]     = (v0-m)*inv*g[tid]     + b[tid];
    yr[tid+256] = (v1-m)*inv*g[tid+256] + b[tid+256];
    yr[tid+512] = (v2-m)*inv*g[tid+512] + b[tid+512];
}

// ---------------- SGEMM: C[M,N] = A[M,K] @ W[N,K]^T + bias (+optional gelu) ------
// 64x64 tile, K-tile 16, 256 threads, 4x4 per thread.
template<int ACT>
__global__ void k_gemm(const float* __restrict__ A, const float* __restrict__ W,
                       const float* __restrict__ bias, float* __restrict__ C,
                       int M, int N, int K){
    __shared__ __align__(16) float As[16][64];
    __shared__ __align__(16) float Bs[16][64];
    int tid  = threadIdx.x;
    int row0 = blockIdx.y*64, col0 = blockIdx.x*64;
    int tm = (tid >> 4) << 2;   // 0..60
    int tn = (tid & 15) << 2;   // 0..60
    float acc[4][4] = {};
    for (int k0 = 0; k0 < K; k0 += 16){
        #pragma unroll
        for (int i = 0; i < 4; i++){
            int idx = tid + (i << 8);      // 0..1023
            int mm = idx >> 4, kk = idx & 15;
            As[kk][mm] = (row0+mm < M) ? A[(size_t)(row0+mm)*K + k0+kk] : 0.f;
            Bs[kk][mm] = (col0+mm < N) ? W[(size_t)(col0+mm)*K + k0+kk] : 0.f;
        }
        __syncthreads();
        #pragma unroll
        for (int kk = 0; kk < 16; kk++){
            float4 av = *reinterpret_cast<const float4*>(&As[kk][tm]);
            float4 bv = *reinterpret_cast<const float4*>(&Bs[kk][tn]);
            float aa[4] = {av.x, av.y, av.z, av.w};
            float bb[4] = {bv.x, bv.y, bv.z, bv.w};
            #pragma unroll
            for (int i = 0; i < 4; i++)
                #pragma unroll
                for (int j = 0; j < 4; j++)
                    acc[i][j] += aa[i]*bb[j];
        }
        __syncthreads();
    }
    #pragma unroll
    for (int i = 0; i < 4; i++){
        int r = row0 + tm + i;
        if (r >= M) continue;
        #pragma unroll
        for (int j = 0; j < 4; j++){
            int c = col0 + tn + j;
            if (c >= N) continue;
            float v = acc[i][j] + (bias ? bias[c] : 0.f);
            if (ACT == 1) v = gelu_exact(v);
            C[(size_t)r*N + c] = v;
        }
    }
}

// ---------------- attention (per (batch, head) block) ----------------
__global__ void k_attn(const float* __restrict__ q, const float* __restrict__ k,
                       const float* __restrict__ v, float* __restrict__ o){
    int b = blockIdx.x / NHh, hh = blockIdx.x % NHh;
    int tid = threadIdx.x;
    __shared__ float qs[Sz][HDd], ks[Sz][HDd], vs[Sz][HDd];
    __shared__ float sc[Sz][32];
    for (int idx = tid; idx < Sz*HDd; idx += 256){
        int s = idx / HDd, dd = idx % HDd;
        size_t off = ((size_t)(b*Sz + s))*Hs + hh*HDd + dd;
        qs[s][dd] = q[off]; ks[s][dd] = k[off]; vs[s][dd] = v[off];
    }
    __syncthreads();
    for (int idx = tid; idx < Sz*Sz; idx += 256){
        int i = idx / Sz, j = idx % Sz;
        float s = 0.f;
        #pragma unroll
        for (int dd = 0; dd < HDd; dd++) s += qs[i][dd]*ks[j][dd];
        sc[i][j] = s * 0.125f;    // 1/sqrt(64)
    }
    __syncthreads();
    if (tid < Sz){
        float mx = -1e30f;
        for (int j = 0; j < Sz; j++) mx = fmaxf(mx, sc[tid][j]);
        float sm = 0.f;
        for (int j = 0; j < Sz; j++){ float e = expf(sc[tid][j]-mx); sc[tid][j] = e; sm += e; }
        float inv = 1.f/sm;
        for (int j = 0; j < Sz; j++) sc[tid][j] *= inv;
    }
    __syncthreads();
    for (int idx = tid; idx < Sz*HDd; idx += 256){
        int i = idx / HDd, dd = idx % HDd;
        float s = 0.f;
        for (int j = 0; j < Sz; j++) s += sc[i][j]*vs[j][dd];
        o[((size_t)(b*Sz + i))*Hs + hh*HDd + dd] = s;
    }
}

// ---------------- mask prep: maskf = (mask>0), cnt = col sums ----------------
__global__ void k_prep(const float* __restrict__ mask, float* __restrict__ maskf,
                       float* __restrict__ cnt){
    int d = threadIdx.x;
    if (d < Dd){
        float s = 0.f;
        for (int r = 0; r < Rr; r++){
            float f = (mask[r*Dd+d] > 0.f) ? 1.f : 0.f;
            maskf[r*Dd+d] = f; s += f;
        }
        cnt[d] = s;
    }
}

// ---------------- pooled[d][b][:] = sum_r maskf[r,d]*att[b,1+r,:] / max(cnt,1) ----
__global__ void k_pool(const float* __restrict__ att, const float* __restrict__ maskf,
                       const float* __restrict__ cnt, float* __restrict__ pooled){
    int d = blockIdx.x / Bz, b = blockIdx.x % Bz;
    int tid = threadIdx.x;
    __shared__ float msk[Rr];
    if (tid < Rr) msk[tid] = maskf[tid*Dd + d];
    __syncthreads();
    float inv = 1.f / fmaxf(cnt[d], 1.f);
    #pragma unroll
    for (int j = 0; j < 3; j++){
        int hh = tid + j*256;
        float s = 0.f;
        for (int r = 0; r < Rr; r++)
            if (msk[r] != 0.f) s += att[((size_t)(b*Sz) + 1 + r)*Hs + hh];
        pooled[((size_t)(d*Bz + b))*Hs + hh] = s*inv;
    }
}

// ---------------- per-(b,d) classifier -> active flag ----------------
__global__ void k_cls(const float* __restrict__ pooled, const float* __restrict__ cw1,
                      const float* __restrict__ cb1, const float* __restrict__ clg,
                      const float* __restrict__ clb, const float* __restrict__ cw2,
                      const float* __restrict__ cb2, const float* __restrict__ cnt,
                      float* __restrict__ actd){
    int d = blockIdx.x / Bz, b = blockIdx.x % Bz;
    int tid = threadIdx.x;   // 128 threads
    __shared__ float pol[Hs];
    __shared__ float h1[384];
    __shared__ float red[128], red2[128], stats[2];
    for (int i = tid; i < Hs; i += 128) pol[i] = pooled[((size_t)(d*Bz+b))*Hs + i];
    __syncthreads();
    for (int kx = tid; kx < 384; kx += 128){
        const float* wrow = cw1 + ((size_t)(d*384 + kx))*Hs;
        float s = cb1[d*384 + kx];
        for (int hh = 0; hh < Hs; hh++) s += pol[hh]*wrow[hh];
        h1[kx] = s;
    }
    __syncthreads();
    float l1 = 0.f, l2 = 0.f;
    for (int kx = tid; kx < 384; kx += 128){ float v = h1[kx]; l1 += v; l2 += v*v; }
    red[tid] = l1; red2[tid] = l2;
    __syncthreads();
    for (int st = 64; st > 0; st >>= 1){
        if (tid < st){ red[tid]+=red[tid+st]; red2[tid]+=red2[tid+st]; }
        __syncthreads();
    }
    if (tid == 0){
        float m = red[0]/384.f;
        stats[0] = m;
        stats[1] = rsqrtf(red2[0]/384.f - m*m + 1e-5f);
    }
    __syncthreads();
    float m = stats[0], inv = stats[1];
    float dot = 0.f;
    for (int kx = tid; kx < 384; kx += 128){
        float v = (h1[kx]-m)*inv*clg[d*384+kx] + clb[d*384+kx];
        v = gelu_exact(v);
        dot += v*cw2[d*384+kx];
    }
    __syncthreads();                 // red reuse
    red[tid] = dot;
    __syncthreads();
    for (int st = 64; st > 0; st >>= 1){
        if (tid < st) red[tid] += red[tid+st];
        __syncthreads();
    }
    if (tid == 0){
        float pred = red[0] + cb2[d];
        // sigmoid(pred)>0.5 <=> pred>0 ; cnt==0 forces pred->0 -> inactive
        actd[b*Dd + d] = (cnt[d] > 0.f && pred > 0.f) ? 1.f : 0.f;
    }
}

// ---------------- routing coefficients coef[t][e] = active*w ----------------
__global__ void k_route(const float* __restrict__ actd, const float* __restrict__ maskf,
                        float* __restrict__ coef){
    int t = blockIdx.x*256 + threadIdx.x;
    if (t >= TOK) return;
    int b = t / Sz, s = t % Sz;
    float a[Dd]; float c = 1.f;
    #pragma unroll
    for (int d = 0; d < Dd; d++){
        float f = (s > 0) ? actd[b*Dd+d]*maskf[(s-1)*Dd+d] : 0.f;
        a[d] = f; c += f;
    }
    float w = 1.f / c;     // c >= 1 always (general expert)
    #pragma unroll
    for (int d = 0; d < Dd; d++) coef[t*Ee + d] = a[d]*w;
    coef[t*Ee + Dd] = w;
}

// ---------------- M_e[r'][r] = sum_i Ad[e,r',i]*Bu[e,i,r]  (8x8 per expert) ----
__global__ void k_loraM(const float* __restrict__ ad, const float* __restrict__ bu,
                        float* __restrict__ M){
    int e = blockIdx.x, idx = threadIdx.x;   // 64 threads
    int rp = idx / LRr, r = idx % LRr;
    const float* Ad = ad + ((size_t)e*LRr + rp)*Is;
    const float* Bu = bu + (size_t)e*Is*LRr + r;
    float s = 0.f;
    for (int i = 0; i < Is; i++) s += Ad[i]*Bu[(size_t)i*LRr];
    M[e*64 + idx] = s;
}

// ---------------- fused expert mix: h = sum_e coef*LN(base_out + down_e) + res1 ----
__global__ void k_mix(const float* __restrict__ bout, const float* __restrict__ res1,
                      const float* __restrict__ t1, const float* __restrict__ g,
                      const float* __restrict__ M, const float* __restrict__ Bd,
                      const float* __restrict__ coef, float* __restrict__ hout){
    int t = blockIdx.x, tid = threadIdx.x;   // 256 threads, 3 h/thread
    __shared__ float gsh[LRr];
    __shared__ float red[256], red2[256], stats[2];
    float bo[3], r1[3], acc[3] = {0.f, 0.f, 0.f};
    #pragma unroll
    for (int j = 0; j < 3; j++){
        int hh = tid + j*256;
        bo[j] = bout[(size_t)t*Hs + hh];
        r1[j] = res1[(size_t)t*Hs + hh];
    }
    for (int e = 0; e < Ee; e++){
        float c = coef[t*Ee + e];      // uniform across the block
        if (c == 0.f) continue;
        __syncthreads();               // protect gsh/red reuse
        if (tid < LRr){
            float s = g[(size_t)t*(Ee*LRr) + e*LRr + tid];
            #pragma unroll
            for (int r = 0; r < LRr; r++)
                s += LORA_SCAL * t1[(size_t)t*(Ee*LRr) + e*LRr + r] * M[e*64 + tid*LRr + r];
            gsh[tid] = s;
        }
        __syncthreads();
        float o[3]; float l1 = 0.f, l2 = 0.f;
        #pragma unroll
        for (int j = 0; j < 3; j++){
            int hh = tid + j*256;
            const float* bdrow = Bd + ((size_t)e*Hs + hh)*LRr;
            float dn = 0.f;
            #pragma unroll
            for (int rp = 0; rp < LRr; rp++) dn += gsh[rp]*bdrow[rp];
            o[j] = bo[j] + LORA_SCAL*dn;
            l1 += o[j]; l2 += o[j]*o[j];
        }
        red[tid] = l1; red2[tid] = l2;
        __syncthreads();
        for (int st = 128; st > 0; st >>= 1){
            if (tid < st){ red[tid]+=red[tid+st]; red2[tid]+=red2[tid+st]; }
            __syncthreads();
        }
        if (tid == 0){
            float m = red[0]/768.f;
            stats[0] = m;
            stats[1] = rsqrtf(red2[0]/768.f - m*m + 1e-5f);
        }
        __syncthreads();
        float m = stats[0], inv = stats[1];
        #pragma unroll
        for (int j = 0; j < 3; j++) acc[j] += c*(o[j]-m)*inv;
    }
    #pragma unroll
    for (int j = 0; j < 3; j++)
        hout[(size_t)t*Hs + tid + j*256] = acc[j] + r1[j];
}

// ============================ host launch ============================
extern "C" void kernel_launch(void* const* d_in, const int* in_sizes, int n_in,
                              void* d_out, int out_size){
    const float* region = (const float*)d_in[0];
    const float* cls    = (const float*)d_in[1];
    const float* ln1g   = (const float*)d_in[2];
    const float* ln1b   = (const float*)d_in[3];
    const float* ln2g   = (const float*)d_in[4];
    const float* ln2b   = (const float*)d_in[5];
    const float* wq     = (const float*)d_in[6];
    const float* bq     = (const float*)d_in[7];
    const float* wk     = (const float*)d_in[8];
    const float* bk     = (const float*)d_in[9];
    const float* wv     = (const float*)d_in[10];
    const float* bv     = (const float*)d_in[11];
    const float* wo     = (const float*)d_in[12];
    const float* bo     = (const float*)d_in[13];
    const float* wi     = (const float*)d_in[14];
    const float* bi     = (const float*)d_in[15];
    const float* wof    = (const float*)d_in[16];
    const float* bof    = (const float*)d_in[17];
    const float* lnfg   = (const float*)d_in[18];
    const float* lnfb   = (const float*)d_in[19];
    const float* au     = (const float*)d_in[20];
    const float* bu     = (const float*)d_in[21];
    const float* ad     = (const float*)d_in[22];
    const float* bd     = (const float*)d_in[23];
    const float* cw1    = (const float*)d_in[24];
    const float* cb1    = (const float*)d_in[25];
    const float* clg    = (const float*)d_in[26];
    const float* clb    = (const float*)d_in[27];
    const float* cw2    = (const float*)d_in[28];
    const float* cb2    = (const float*)d_in[29];
    const float* maskI  = (const float*)d_in[30];

    float *ph, *pnx, *pq, *pk, *pv, *pattc, *patt, *pres1, *pnres, *phid, *pbout;
    float *pt1, *pg, *ppool, *pcoef, *pM, *pmaskf, *pcnt, *pactd;
    cudaGetSymbolAddress((void**)&ph,    d_h);
    cudaGetSymbolAddress((void**)&pnx,   d_nx);
    cudaGetSymbolAddress((void**)&pq,    d_qb);
    cudaGetSymbolAddress((void**)&pk,    d_kb);
    cudaGetSymbolAddress((void**)&pv,    d_vb);
    cudaGetSymbolAddress((void**)&pattc, d_attc);
    cudaGetSymbolAddress((void**)&patt,  d_att);
    cudaGetSymbolAddress((void**)&pres1, d_res1);
    cudaGetSymbolAddress((void**)&pnres, d_nres);
    cudaGetSymbolAddress((void**)&phid,  d_hid);
    cudaGetSymbolAddress((void**)&pbout, d_bout);
    cudaGetSymbolAddress((void**)&pt1,   d_t1);
    cudaGetSymbolAddress((void**)&pg,    d_g);
    cudaGetSymbolAddress((void**)&ppool, d_pooled);
    cudaGetSymbolAddress((void**)&pcoef, d_coef);
    cudaGetSymbolAddress((void**)&pM,    d_M);
    cudaGetSymbolAddress((void**)&pmaskf,d_maskf);
    cudaGetSymbolAddress((void**)&pcnt,  d_cnt);
    cudaGetSymbolAddress((void**)&pactd, d_actd);

    const int NEL = TOK*Hs;
    dim3 g768((768+63)/64, (TOK+63)/64);
    dim3 gup ((Is +63)/64, (TOK+63)/64);
    dim3 g120((120+63)/64, (TOK+63)/64);

    k_build<<<(NEL+255)/256, 256>>>(region, cls, ph);
    k_prep<<<1, 32>>>(maskI, pmaskf, pcnt);

    int ei = 0;
    for (int i = 0; i < 12; i++){
        k_ln<<<TOK, 256>>>(ph, pnx, ln1g + i*Hs, ln1b + i*Hs, 1e-12f);
        k_gemm<0><<<g768, 256>>>(pnx, wq + (size_t)i*Hs*Hs, bq + i*Hs, pq, TOK, Hs, Hs);
        k_gemm<0><<<g768, 256>>>(pnx, wk + (size_t)i*Hs*Hs, bk + i*Hs, pk, TOK, Hs, Hs);
        k_gemm<0><<<g768, 256>>>(pnx, wv + (size_t)i*Hs*Hs, bv + i*Hs, pv, TOK, Hs, Hs);
        k_attn<<<Bz*NHh, 256>>>(pq, pk, pv, pattc);
        k_gemm<0><<<g768, 256>>>(pattc, wo + (size_t)i*Hs*Hs, bo + i*Hs, patt, TOK, Hs, Hs);
        k_add<<<(NEL+255)/256, 256>>>(patt, ph, pres1, NEL);
        k_ln<<<TOK, 256>>>(pres1, pnres, ln2g + i*Hs, ln2b + i*Hs, 1e-12f);
        k_gemm<1><<<gup, 256>>>(pnres, wi + (size_t)i*Is*Hs, bi + i*Is, phid, TOK, Is, Hs);
        k_gemm<0><<<g768, 256>>>(phid, wof + (size_t)i*Hs*Is, bof + i*Hs, pbout, TOK, Hs, Is);

        if (i % 2 == 1){
            k_add<<<(NEL+255)/256, 256>>>(pres1, pbout, ph, NEL);
        } else {
            // classifiers -> routing
            k_pool<<<Dd*Bz, 256>>>(patt, pmaskf, pcnt, ppool);
            k_cls<<<Dd*Bz, 128>>>(ppool,
                                  cw1 + (size_t)ei*Dd*384*Hs, cb1 + (size_t)ei*Dd*384,
                                  clg + (size_t)ei*Dd*384,    clb + (size_t)ei*Dd*384,
                                  cw2 + (size_t)ei*Dd*384,    cb2 + (size_t)ei*Dd,
                                  pcnt, pactd);
            k_route<<<(TOK+255)/256, 256>>>(pactd, pmaskf, pcoef);
            // LoRA: M_e = Ad_e @ Bu_e ; t1 = nres@Au^T ; g = base_hidden@Ad^T
            k_loraM<<<Ee, 64>>>(ad + (size_t)ei*Ee*LRr*Is, bu + (size_t)ei*Ee*Is*LRr, pM);
            k_gemm<0><<<g120, 256>>>(pnres, au + (size_t)ei*Ee*LRr*Hs, (const float*)nullptr,
                                     pt1, TOK, Ee*LRr, Hs);
            k_gemm<0><<<g120, 256>>>(phid, ad + (size_t)ei*Ee*LRr*Is, (const float*)nullptr,
                                     pg, TOK, Ee*LRr, Is);
            k_mix<<<TOK, 256>>>(pbout, pres1, pt1, pg, pM,
                                bd + (size_t)ei*Ee*Hs*LRr, pcoef, ph);
            ei++;
        }
    }
    k_ln<<<TOK, 256>>>(ph, (float*)d_out, lnfg, lnfb, 1e-12f);
}

// round 5
// speedup vs baseline: 1.6978x; 1.6978x over previous
#include <cuda_runtime.h>
#include <math.h>
#include <stdint.h>

#define Bz   128
#define Sz   30
#define Hs   768
#define Is   3072
#define NHh  12
#define HDd  64
#define TOK  (Bz*Sz)     // 3840
#define Ee   15
#define Dd   14
#define Rr   29
#define LRr  8
#define LORA_SCAL 2.0f

// ---------------- scratch (static __device__, no allocations) ----------------
__device__ float d_h    [TOK*Hs];
__device__ float d_nx   [TOK*Hs];
__device__ float d_qb   [TOK*Hs];
__device__ float d_kb   [TOK*Hs];
__device__ float d_vb   [TOK*Hs];
__device__ float d_attc [TOK*Hs];   // attention context (pre O-proj)
__device__ float d_att  [TOK*Hs];   // post O-proj (needed by classifier)
__device__ float d_res1 [TOK*Hs];
__device__ float d_nres [TOK*Hs];
__device__ float d_hid  [TOK*Is];   // base_hidden (post-gelu FFN up)
__device__ float d_bout [TOK*Hs];   // base_out
__device__ float d_t1   [TOK*(Ee*LRr)];   // nres @ Au_all^T
__device__ float d_g    [TOK*(Ee*LRr)];   // base_hidden @ Ad_all^T
__device__ float d_pooled[Dd*Bz*Hs];
__device__ float d_coef [TOK*Ee];
__device__ float d_M    [Ee*LRr*LRr];     // per even layer: Ad_e @ Bu_e (8x8)
__device__ float d_maskf[Rr*Dd];
__device__ float d_cnt  [Dd];
__device__ float d_actd [Bz*Dd];

// ---------------- helpers ----------------
__device__ __forceinline__ float gelu_exact(float x){
    return 0.5f * x * (1.f + erff(x * 0.70710678118654752f));
}

__device__ __forceinline__ unsigned f2tf32(float x){
    unsigned u;
    asm("cvt.rna.tf32.f32 %0, %1;" : "=r"(u) : "f"(x));
    return u;
}
__device__ __forceinline__ void tf32split(float x, unsigned& h, unsigned& l){
    h = f2tf32(x);
    l = f2tf32(x - __uint_as_float(h));
}
__device__ __forceinline__ void mma_tf32(float* c, const unsigned* a, const unsigned* b){
    asm volatile(
        "mma.sync.aligned.m16n8k8.row.col.f32.tf32.tf32.f32 "
        "{%0,%1,%2,%3}, {%4,%5,%6,%7}, {%8,%9}, {%0,%1,%2,%3};"
        : "+f"(c[0]), "+f"(c[1]), "+f"(c[2]), "+f"(c[3])
        : "r"(a[0]), "r"(a[1]), "r"(a[2]), "r"(a[3]), "r"(b[0]), "r"(b[1]));
}
__device__ __forceinline__ void cpa16(uint32_t dst, const float* src, bool v){
    int sz = v ? 16 : 0;
    asm volatile("cp.async.cg.shared.global [%0], [%1], 16, %2;"
                 :: "r"(dst), "l"(src), "r"(sz));
}

// ---------------- build initial h = [cls ; region_features] ----------------
__global__ void k_build(const float* __restrict__ region, const float* __restrict__ cls,
                        float* __restrict__ h){
    int i = blockIdx.x*256 + threadIdx.x;
    if (i >= TOK*Hs) return;
    int t = i / Hs, hh = i % Hs;
    int b = t / Sz, s = t % Sz;
    h[i] = (s == 0) ? cls[hh] : region[((size_t)b*Rr + (s-1))*Hs + hh];
}

// ---------------- elementwise add ----------------
__global__ void k_add(const float* __restrict__ a, const float* __restrict__ b,
                      float* __restrict__ c, int n){
    int i = blockIdx.x*256 + threadIdx.x;
    if (i < n) c[i] = a[i] + b[i];
}

// ---------------- layernorm over H=768 (256 thr, 3 elems/thread) ----------------
__global__ void k_ln(const float* __restrict__ x, float* __restrict__ y,
                     const float* __restrict__ g, const float* __restrict__ b, float eps){
    int t = blockIdx.x, tid = threadIdx.x;
    const float* xr = x + (size_t)t*Hs;
    float v0 = xr[tid], v1 = xr[tid+256], v2 = xr[tid+512];
    __shared__ float red[256], red2[256], mi[2];
    red[tid]  = v0+v1+v2;
    red2[tid] = v0*v0+v1*v1+v2*v2;
    __syncthreads();
    for (int st = 128; st > 0; st >>= 1){
        if (tid < st){ red[tid]+=red[tid+st]; red2[tid]+=red2[tid+st]; }
        __syncthreads();
    }
    if (tid == 0){
        float m = red[0]/768.f;
        float var = red2[0]/768.f - m*m;
        mi[0] = m; mi[1] = rsqrtf(var + eps);
    }
    __syncthreads();
    float m = mi[0], inv = mi[1];
    float* yr = y + (size_t)t*Hs;
    yr[tid]     = (v0-m)*inv*g[tid]     + b[tid];
    yr[tid+256] = (v1-m)*inv*g[tid+256] + b[tid+256];
    yr[tid+512] = (v2-m)*inv*g[tid+512] + b[tid+512];
}

// ---------------- 3xTF32 tensor-core GEMM ----------------
// C[M,N] = A[M,K] @ W[N,K]^T + bias (+optional exact gelu)
// Block tile 128x64, BK=16, 256 threads (8 warps, 4x2), warp tile 32x32.
// Double-buffered cp.async. Smem row stride 20 floats -> conflict-free LDS.
template<int ACT>
__global__ void __launch_bounds__(256) k_gemm(const float* __restrict__ A,
                       const float* __restrict__ W,
                       const float* __restrict__ bias, float* __restrict__ C,
                       int M, int N, int K){
    __shared__ __align__(16) float As[2][128*20];
    __shared__ __align__(16) float Bs[2][64*20];
    int tid  = threadIdx.x;
    int row0 = blockIdx.y*128, col0 = blockIdx.x*64;
    int wid  = tid >> 5, lane = tid & 31;
    int wm   = wid >> 1, wn = wid & 1;       // warp 4x2
    int q    = lane >> 2, r = lane & 3;

    float acc[2][4][4];
    #pragma unroll
    for (int i=0;i<2;i++) for (int j=0;j<4;j++) for (int kx=0;kx<4;kx++) acc[i][j][kx]=0.f;

    // cp.async tile assignment
    int am0 = tid >> 2,            ak0 = (tid & 3) * 4;         // A float4 #tid
    int am1 = (tid+256) >> 2,      ak1 = ak0;                    // A float4 #tid+256
    int bn  = tid >> 2,            bk  = (tid & 3) * 4;          // B float4 #tid

    uint32_t sa0 = (uint32_t)__cvta_generic_to_shared(&As[0][0]);
    uint32_t sa1 = (uint32_t)__cvta_generic_to_shared(&As[1][0]);
    uint32_t sb0 = (uint32_t)__cvta_generic_to_shared(&Bs[0][0]);
    uint32_t sb1 = (uint32_t)__cvta_generic_to_shared(&Bs[1][0]);

    bool va0 = (row0 + am0) < M;
    bool va1 = (row0 + am1) < M;
    bool vb  = (col0 + bn)  < N;

    const float* pa0 = A + (size_t)(row0+am0)*K + ak0;
    const float* pa1 = A + (size_t)(row0+am1)*K + ak1;
    const float* pw  = W + (size_t)(col0+bn)*K + bk;

    // prologue: tile 0 -> buf 0
    cpa16(sa0 + (uint32_t)(am0*20 + ak0)*4u, pa0, va0);
    cpa16(sa0 + (uint32_t)(am1*20 + ak1)*4u, pa1, va1);
    cpa16(sb0 + (uint32_t)(bn *20 + bk )*4u, pw,  vb);
    asm volatile("cp.async.commit_group;");

    int T = K >> 4;
    for (int t = 0; t < T; t++){
        asm volatile("cp.async.wait_group 0;");
        __syncthreads();
        if (t+1 < T){
            int k0 = (t+1) << 4;
            uint32_t sa = ((t+1)&1) ? sa1 : sa0;
            uint32_t sb = ((t+1)&1) ? sb1 : sb0;
            cpa16(sa + (uint32_t)(am0*20 + ak0)*4u, pa0 + k0, va0);
            cpa16(sa + (uint32_t)(am1*20 + ak1)*4u, pa1 + k0, va1);
            cpa16(sb + (uint32_t)(bn *20 + bk )*4u, pw  + k0, vb);
            asm volatile("cp.async.commit_group;");
        }
        const float* as = As[t&1];
        const float* bs = Bs[t&1];
        #pragma unroll
        for (int ks = 0; ks < 16; ks += 8){
            unsigned ah[2][4], al[2][4], bh[4][2], bl[4][2];
            #pragma unroll
            for (int mt = 0; mt < 2; mt++){
                int m0 = wm*32 + mt*16;
                float f0 = as[(m0+q  )*20 + ks + r    ];
                float f1 = as[(m0+q+8)*20 + ks + r    ];
                float f2 = as[(m0+q  )*20 + ks + r + 4];
                float f3 = as[(m0+q+8)*20 + ks + r + 4];
                tf32split(f0, ah[mt][0], al[mt][0]);
                tf32split(f1, ah[mt][1], al[mt][1]);
                tf32split(f2, ah[mt][2], al[mt][2]);
                tf32split(f3, ah[mt][3], al[mt][3]);
            }
            #pragma unroll
            for (int nt = 0; nt < 4; nt++){
                int n0 = wn*32 + nt*8;
                float g0 = bs[(n0+q)*20 + ks + r    ];
                float g1 = bs[(n0+q)*20 + ks + r + 4];
                tf32split(g0, bh[nt][0], bl[nt][0]);
                tf32split(g1, bh[nt][1], bl[nt][1]);
            }
            #pragma unroll
            for (int mt = 0; mt < 2; mt++)
                #pragma unroll
                for (int nt = 0; nt < 4; nt++){
                    mma_tf32(acc[mt][nt], ah[mt], bh[nt]);   // hi*hi
                    mma_tf32(acc[mt][nt], al[mt], bh[nt]);   // lo*hi
                    mma_tf32(acc[mt][nt], ah[mt], bl[nt]);   // hi*lo
                }
        }
        __syncthreads();
    }

    // epilogue
    #pragma unroll
    for (int mt = 0; mt < 2; mt++){
        int Rbase = row0 + wm*32 + mt*16 + q;
        #pragma unroll
        for (int nt = 0; nt < 4; nt++){
            int Cbase = col0 + wn*32 + nt*8 + 2*r;
            #pragma unroll
            for (int cc = 0; cc < 4; cc++){
                int rr = Rbase + ((cc >= 2) ? 8 : 0);
                int cl = Cbase + (cc & 1);
                if (rr < M && cl < N){
                    float v = acc[mt][nt][cc] + (bias ? bias[cl] : 0.f);
                    if (ACT == 1) v = gelu_exact(v);
                    C[(size_t)rr*N + cl] = v;
                }
            }
        }
    }
}

// ---------------- attention (per (batch, head) block) ----------------
__global__ void k_attn(const float* __restrict__ q, const float* __restrict__ k,
                       const float* __restrict__ v, float* __restrict__ o){
    int b = blockIdx.x / NHh, hh = blockIdx.x % NHh;
    int tid = threadIdx.x;
    __shared__ float qs[Sz][HDd], ks[Sz][HDd], vs[Sz][HDd];
    __shared__ float sc[Sz][32];
    for (int idx = tid; idx < Sz*HDd; idx += 256){
        int s = idx / HDd, dd = idx % HDd;
        size_t off = ((size_t)(b*Sz + s))*Hs + hh*HDd + dd;
        qs[s][dd] = q[off]; ks[s][dd] = k[off]; vs[s][dd] = v[off];
    }
    __syncthreads();
    for (int idx = tid; idx < Sz*Sz; idx += 256){
        int i = idx / Sz, j = idx % Sz;
        float s = 0.f;
        #pragma unroll
        for (int dd = 0; dd < HDd; dd++) s += qs[i][dd]*ks[j][dd];
        sc[i][j] = s * 0.125f;    // 1/sqrt(64)
    }
    __syncthreads();
    if (tid < Sz){
        float mx = -1e30f;
        for (int j = 0; j < Sz; j++) mx = fmaxf(mx, sc[tid][j]);
        float sm = 0.f;
        for (int j = 0; j < Sz; j++){ float e = expf(sc[tid][j]-mx); sc[tid][j] = e; sm += e; }
        float inv = 1.f/sm;
        for (int j = 0; j < Sz; j++) sc[tid][j] *= inv;
    }
    __syncthreads();
    for (int idx = tid; idx < Sz*HDd; idx += 256){
        int i = idx / HDd, dd = idx % HDd;
        float s = 0.f;
        for (int j = 0; j < Sz; j++) s += sc[i][j]*vs[j][dd];
        o[((size_t)(b*Sz + i))*Hs + hh*HDd + dd] = s;
    }
}

// ---------------- mask prep: maskf = (mask>0), cnt = col sums ----------------
__global__ void k_prep(const float* __restrict__ mask, float* __restrict__ maskf,
                       float* __restrict__ cnt){
    int d = threadIdx.x;
    if (d < Dd){
        float s = 0.f;
        for (int r = 0; r < Rr; r++){
            float f = (mask[r*Dd+d] > 0.f) ? 1.f : 0.f;
            maskf[r*Dd+d] = f; s += f;
        }
        cnt[d] = s;
    }
}

// ---------------- pooled[d][b][:] = sum_r maskf[r,d]*att[b,1+r,:] / max(cnt,1) ----
__global__ void k_pool(const float* __restrict__ att, const float* __restrict__ maskf,
                       const float* __restrict__ cnt, float* __restrict__ pooled){
    int d = blockIdx.x / Bz, b = blockIdx.x % Bz;
    int tid = threadIdx.x;
    __shared__ float msk[Rr];
    if (tid < Rr) msk[tid] = maskf[tid*Dd + d];
    __syncthreads();
    float inv = 1.f / fmaxf(cnt[d], 1.f);
    #pragma unroll
    for (int j = 0; j < 3; j++){
        int hh = tid + j*256;
        float s = 0.f;
        for (int r = 0; r < Rr; r++)
            if (msk[r] != 0.f) s += att[((size_t)(b*Sz) + 1 + r)*Hs + hh];
        pooled[((size_t)(d*Bz + b))*Hs + hh] = s*inv;
    }
}

// ---------------- per-(b,d) classifier -> active flag ----------------
__global__ void k_cls(const float* __restrict__ pooled, const float* __restrict__ cw1,
                      const float* __restrict__ cb1, const float* __restrict__ clg,
                      const float* __restrict__ clb, const float* __restrict__ cw2,
                      const float* __restrict__ cb2, const float* __restrict__ cnt,
                      float* __restrict__ actd){
    int d = blockIdx.x / Bz, b = blockIdx.x % Bz;
    int tid = threadIdx.x;   // 128 threads
    __shared__ float pol[Hs];
    __shared__ float h1[384];
    __shared__ float red[128], red2[128], stats[2];
    for (int i = tid; i < Hs; i += 128) pol[i] = pooled[((size_t)(d*Bz+b))*Hs + i];
    __syncthreads();
    for (int kx = tid; kx < 384; kx += 128){
        const float* wrow = cw1 + ((size_t)(d*384 + kx))*Hs;
        float s = cb1[d*384 + kx];
        for (int hh = 0; hh < Hs; hh++) s += pol[hh]*wrow[hh];
        h1[kx] = s;
    }
    __syncthreads();
    float l1 = 0.f, l2 = 0.f;
    for (int kx = tid; kx < 384; kx += 128){ float v = h1[kx]; l1 += v; l2 += v*v; }
    red[tid] = l1; red2[tid] = l2;
    __syncthreads();
    for (int st = 64; st > 0; st >>= 1){
        if (tid < st){ red[tid]+=red[tid+st]; red2[tid]+=red2[tid+st]; }
        __syncthreads();
    }
    if (tid == 0){
        float m = red[0]/384.f;
        stats[0] = m;
        stats[1] = rsqrtf(red2[0]/384.f - m*m + 1e-5f);
    }
    __syncthreads();
    float m = stats[0], inv = stats[1];
    float dot = 0.f;
    for (int kx = tid; kx < 384; kx += 128){
        float v = (h1[kx]-m)*inv*clg[d*384+kx] + clb[d*384+kx];
        v = gelu_exact(v);
        dot += v*cw2[d*384+kx];
    }
    __syncthreads();                 // red reuse
    red[tid] = dot;
    __syncthreads();
    for (int st = 64; st > 0; st >>= 1){
        if (tid < st) red[tid] += red[tid+st];
        __syncthreads();
    }
    if (tid == 0){
        float pred = red[0] + cb2[d];
        actd[b*Dd + d] = (cnt[d] > 0.f && pred > 0.f) ? 1.f : 0.f;
    }
}

// ---------------- routing coefficients coef[t][e] = active*w ----------------
__global__ void k_route(const float* __restrict__ actd, const float* __restrict__ maskf,
                        float* __restrict__ coef){
    int t = blockIdx.x*256 + threadIdx.x;
    if (t >= TOK) return;
    int b = t / Sz, s = t % Sz;
    float a[Dd]; float c = 1.f;
    #pragma unroll
    for (int d = 0; d < Dd; d++){
        float f = (s > 0) ? actd[b*Dd+d]*maskf[(s-1)*Dd+d] : 0.f;
        a[d] = f; c += f;
    }
    float w = 1.f / c;     // c >= 1 always (general expert)
    #pragma unroll
    for (int d = 0; d < Dd; d++) coef[t*Ee + d] = a[d]*w;
    coef[t*Ee + Dd] = w;
}

// ---------------- M_e[r'][r] = sum_i Ad[e,r',i]*Bu[e,i,r]  (8x8 per expert) ----
__global__ void k_loraM(const float* __restrict__ ad, const float* __restrict__ bu,
                        float* __restrict__ M){
    int e = blockIdx.x, idx = threadIdx.x;   // 64 threads
    int rp = idx / LRr, r = idx % LRr;
    const float* Ad = ad + ((size_t)e*LRr + rp)*Is;
    const float* Bu = bu + (size_t)e*Is*LRr + r;
    float s = 0.f;
    for (int i = 0; i < Is; i++) s += Ad[i]*Bu[(size_t)i*LRr];
    M[e*64 + idx] = s;
}

// ---------------- fused expert mix: h = sum_e coef*LN(base_out + down_e) + res1 ----
__global__ void k_mix(const float* __restrict__ bout, const float* __restrict__ res1,
                      const float* __restrict__ t1, const float* __restrict__ g,
                      const float* __restrict__ M, const float* __restrict__ Bd,
                      const float* __restrict__ coef, float* __restrict__ hout){
    int t = blockIdx.x, tid = threadIdx.x;   // 256 threads, 3 h/thread
    __shared__ float gsh[LRr];
    __shared__ float red[256], red2[256], stats[2];
    float bo[3], r1[3], acc[3] = {0.f, 0.f, 0.f};
    #pragma unroll
    for (int j = 0; j < 3; j++){
        int hh = tid + j*256;
        bo[j] = bout[(size_t)t*Hs + hh];
        r1[j] = res1[(size_t)t*Hs + hh];
    }
    for (int e = 0; e < Ee; e++){
        float c = coef[t*Ee + e];      // uniform across the block
        if (c == 0.f) continue;
        __syncthreads();               // protect gsh/red reuse
        if (tid < LRr){
            float s = g[(size_t)t*(Ee*LRr) + e*LRr + tid];
            #pragma unroll
            for (int r = 0; r < LRr; r++)
                s += LORA_SCAL * t1[(size_t)t*(Ee*LRr) + e*LRr + r] * M[e*64 + tid*LRr + r];
            gsh[tid] = s;
        }
        __syncthreads();
        float o[3]; float l1 = 0.f, l2 = 0.f;
        #pragma unroll
        for (int j = 0; j < 3; j++){
            int hh = tid + j*256;
            const float* bdrow = Bd + ((size_t)e*Hs + hh)*LRr;
            float dn = 0.f;
            #pragma unroll
            for (int rp = 0; rp < LRr; rp++) dn += gsh[rp]*bdrow[rp];
            o[j] = bo[j] + LORA_SCAL*dn;
            l1 += o[j]; l2 += o[j]*o[j];
        }
        red[tid] = l1; red2[tid] = l2;
        __syncthreads();
        for (int st = 128; st > 0; st >>= 1){
            if (tid < st){ red[tid]+=red[tid+st]; red2[tid]+=red2[tid+st]; }
            __syncthreads();
        }
        if (tid == 0){
            float m = red[0]/768.f;
            stats[0] = m;
            stats[1] = rsqrtf(red2[0]/768.f - m*m + 1e-5f);
        }
        __syncthreads();
        float m = stats[0], inv = stats[1];
        #pragma unroll
        for (int j = 0; j < 3; j++) acc[j] += c*(o[j]-m)*inv;
    }
    #pragma unroll
    for (int j = 0; j < 3; j++)
        hout[(size_t)t*Hs + tid + j*256] = acc[j] + r1[j];
}

// ============================ host launch ============================
extern "C" void kernel_launch(void* const* d_in, const int* in_sizes, int n_in,
                              void* d_out, int out_size){
    const float* region = (const float*)d_in[0];
    const float* cls    = (const float*)d_in[1];
    const float* ln1g   = (const float*)d_in[2];
    const float* ln1b   = (const float*)d_in[3];
    const float* ln2g   = (const float*)d_in[4];
    const float* ln2b   = (const float*)d_in[5];
    const float* wq     = (const float*)d_in[6];
    const float* bq     = (const float*)d_in[7];
    const float* wk     = (const float*)d_in[8];
    const float* bk     = (const float*)d_in[9];
    const float* wv     = (const float*)d_in[10];
    const float* bv     = (const float*)d_in[11];
    const float* wo     = (const float*)d_in[12];
    const float* bo     = (const float*)d_in[13];
    const float* wi     = (const float*)d_in[14];
    const float* bi     = (const float*)d_in[15];
    const float* wof    = (const float*)d_in[16];
    const float* bof    = (const float*)d_in[17];
    const float* lnfg   = (const float*)d_in[18];
    const float* lnfb   = (const float*)d_in[19];
    const float* au     = (const float*)d_in[20];
    const float* bu     = (const float*)d_in[21];
    const float* ad     = (const float*)d_in[22];
    const float* bd     = (const float*)d_in[23];
    const float* cw1    = (const float*)d_in[24];
    const float* cb1    = (const float*)d_in[25];
    const float* clg    = (const float*)d_in[26];
    const float* clb    = (const float*)d_in[27];
    const float* cw2    = (const float*)d_in[28];
    const float* cb2    = (const float*)d_in[29];
    const float* maskI  = (const float*)d_in[30];

    float *ph, *pnx, *pq, *pk, *pv, *pattc, *patt, *pres1, *pnres, *phid, *pbout;
    float *pt1, *pg, *ppool, *pcoef, *pM, *pmaskf, *pcnt, *pactd;
    cudaGetSymbolAddress((void**)&ph,    d_h);
    cudaGetSymbolAddress((void**)&pnx,   d_nx);
    cudaGetSymbolAddress((void**)&pq,    d_qb);
    cudaGetSymbolAddress((void**)&pk,    d_kb);
    cudaGetSymbolAddress((void**)&pv,    d_vb);
    cudaGetSymbolAddress((void**)&pattc, d_attc);
    cudaGetSymbolAddress((void**)&patt,  d_att);
    cudaGetSymbolAddress((void**)&pres1, d_res1);
    cudaGetSymbolAddress((void**)&pnres, d_nres);
    cudaGetSymbolAddress((void**)&phid,  d_hid);
    cudaGetSymbolAddress((void**)&pbout, d_bout);
    cudaGetSymbolAddress((void**)&pt1,   d_t1);
    cudaGetSymbolAddress((void**)&pg,    d_g);
    cudaGetSymbolAddress((void**)&ppool, d_pooled);
    cudaGetSymbolAddress((void**)&pcoef, d_coef);
    cudaGetSymbolAddress((void**)&pM,    d_M);
    cudaGetSymbolAddress((void**)&pmaskf,d_maskf);
    cudaGetSymbolAddress((void**)&pcnt,  d_cnt);
    cudaGetSymbolAddress((void**)&pactd, d_actd);

    const int NEL = TOK*Hs;
    dim3 g768((768 + 63)/64, (TOK + 127)/128);
    dim3 gup ((Is  + 63)/64, (TOK + 127)/128);
    dim3 g120((120 + 63)/64, (TOK + 127)/128);

    k_build<<<(NEL+255)/256, 256>>>(region, cls, ph);
    k_prep<<<1, 32>>>(maskI, pmaskf, pcnt);

    int ei = 0;
    for (int i = 0; i < 12; i++){
        k_ln<<<TOK, 256>>>(ph, pnx, ln1g + i*Hs, ln1b + i*Hs, 1e-12f);
        k_gemm<0><<<g768, 256>>>(pnx, wq + (size_t)i*Hs*Hs, bq + i*Hs, pq, TOK, Hs, Hs);
        k_gemm<0><<<g768, 256>>>(pnx, wk + (size_t)i*Hs*Hs, bk + i*Hs, pk, TOK, Hs, Hs);
        k_gemm<0><<<g768, 256>>>(pnx, wv + (size_t)i*Hs*Hs, bv + i*Hs, pv, TOK, Hs, Hs);
        k_attn<<<Bz*NHh, 256>>>(pq, pk, pv, pattc);
        k_gemm<0><<<g768, 256>>>(pattc, wo + (size_t)i*Hs*Hs, bo + i*Hs, patt, TOK, Hs, Hs);
        k_add<<<(NEL+255)/256, 256>>>(patt, ph, pres1, NEL);
        k_ln<<<TOK, 256>>>(pres1, pnres, ln2g + i*Hs, ln2b + i*Hs, 1e-12f);
        k_gemm<1><<<gup, 256>>>(pnres, wi + (size_t)i*Is*Hs, bi + i*Is, phid, TOK, Is, Hs);
        k_gemm<0><<<g768, 256>>>(phid, wof + (size_t)i*Hs*Is, bof + i*Hs, pbout, TOK, Hs, Is);

        if (i % 2 == 1){
            k_add<<<(NEL+255)/256, 256>>>(pres1, pbout, ph, NEL);
        } else {
            // classifiers -> routing
            k_pool<<<Dd*Bz, 256>>>(patt, pmaskf, pcnt, ppool);
            k_cls<<<Dd*Bz, 128>>>(ppool,
                                  cw1 + (size_t)ei*Dd*384*Hs, cb1 + (size_t)ei*Dd*384,
                                  clg + (size_t)ei*Dd*384,    clb + (size_t)ei*Dd*384,
                                  cw2 + (size_t)ei*Dd*384,    cb2 + (size_t)ei*Dd,
                                  pcnt, pactd);
            k_route<<<(TOK+255)/256, 256>>>(pactd, pmaskf, pcoef);
            // LoRA: M_e = Ad_e @ Bu_e ; t1 = nres@Au^T ; g = base_hidden@Ad^T
            k_loraM<<<Ee, 64>>>(ad + (size_t)ei*Ee*LRr*Is, bu + (size_t)ei*Ee*Is*LRr, pM);
            k_gemm<0><<<g120, 256>>>(pnres, au + (size_t)ei*Ee*LRr*Hs, (const float*)nullptr,
                                     pt1, TOK, Ee*LRr, Hs);
            k_gemm<0><<<g120, 256>>>(phid, ad + (size_t)ei*Ee*LRr*Is, (const float*)nullptr,
                                     pg, TOK, Ee*LRr, Is);
            k_mix<<<TOK, 256>>>(pbout, pres1, pt1, pg, pM,
                                bd + (size_t)ei*Ee*Hs*LRr, pcoef, ph);
            ei++;
        }
    }
    k_ln<<<TOK, 256>>>(ph, (float*)d_out, lnfg, lnfb, 1e-12f);
}